// round 2
// baseline (speedup 1.0000x reference)
#include <cuda_runtime.h>

#define BATCH 1024

__device__ float g_xT[3 * 32 * 32 * BATCH];   // (C,H,W,B)
__device__ float g_h1[6 * 14 * 14 * BATCH];   // (O1,Ho,Wo,B)
__device__ float g_h2[16 * 25 * BATCH];       // (O2,5,5,B)
__device__ float g_h3[BATCH * 120];           // (B,120)

// ---------------------------------------------------------------------------
// Kernel 0: transpose x (B, 3072) -> xT (3072, B)
// ---------------------------------------------------------------------------
__global__ void k_transpose(const float* __restrict__ x) {
    __shared__ float tile[32][33];
    int f0 = blockIdx.x * 32;
    int b0 = blockIdx.y * 32;
    int tx = threadIdx.x, ty = threadIdx.y;
#pragma unroll
    for (int i = 0; i < 4; i++)
        tile[ty + i * 8][tx] = x[(b0 + ty + i * 8) * 3072 + f0 + tx];
    __syncthreads();
#pragma unroll
    for (int i = 0; i < 4; i++)
        g_xT[(f0 + ty + i * 8) * BATCH + b0 + tx] = tile[tx][ty + i * 8];
}

// ---------------------------------------------------------------------------
// Kernel A: untied conv1 + relu + maxpool. 2 batch items per thread (float2).
// grid (196 pooled positions, 4 batch chunks of 256), block 128
// ---------------------------------------------------------------------------
__global__ void __launch_bounds__(128) k_conv1(const float* __restrict__ w1,
                                               const float* __restrict__ b1) {
    __shared__ float w_s[1800];   // [s][o][c][25]
    __shared__ float bias_s[24];  // [s][o]
    int pos = blockIdx.x;
    int oh = pos / 14, ow = pos % 14;
    int tid = threadIdx.x;

    for (int l = tid; l < 1800; l += 128) {
        int s = l / 450, r = l % 450;
        int o = r / 75, r2 = r % 75;
        int c = r2 / 25, kk = r2 % 25;
        int y = 2 * oh + (s >> 1), x2 = 2 * ow + (s & 1);
        w_s[l] = w1[(((o * 3 + c) * 28 + y) * 28 + x2) * 25 + kk];
    }
    if (tid < 24) {
        int s = tid / 6, o = tid % 6;
        int y = 2 * oh + (s >> 1), x2 = 2 * ow + (s & 1);
        bias_s[tid] = b1[(o * 28 + y) * 28 + x2];
    }
    __syncthreads();

    int b = blockIdx.y * 256 + tid * 2;
    float2 acc[4][6];
#pragma unroll
    for (int s = 0; s < 4; s++)
#pragma unroll
        for (int o = 0; o < 6; o++) {
            float bb = bias_s[s * 6 + o];
            acc[s][o] = make_float2(bb, bb);
        }

    for (int c = 0; c < 3; c++) {
        float2 p[6][6];
#pragma unroll
        for (int iy = 0; iy < 6; iy++)
#pragma unroll
            for (int ix = 0; ix < 6; ix++)
                p[iy][ix] = *(const float2*)&g_xT[((c * 32 + 2 * oh + iy) * 32 + 2 * ow + ix) * BATCH + b];
#pragma unroll
        for (int s = 0; s < 4; s++) {
            int sy = s >> 1, sx = s & 1;
#pragma unroll
            for (int o = 0; o < 6; o++) {
                const float* wp = &w_s[(s * 6 + o) * 75 + c * 25];
                float2 a = acc[s][o];
#pragma unroll
                for (int ky = 0; ky < 5; ky++)
#pragma unroll
                    for (int kx = 0; kx < 5; kx++) {
                        float wv = wp[ky * 5 + kx];
                        a.x += p[sy + ky][sx + kx].x * wv;
                        a.y += p[sy + ky][sx + kx].y * wv;
                    }
                acc[s][o] = a;
            }
        }
    }
#pragma unroll
    for (int o = 0; o < 6; o++) {
        float2 m;
        m.x = fmaxf(fmaxf(fmaxf(acc[0][o].x, acc[1][o].x), fmaxf(acc[2][o].x, acc[3][o].x)), 0.f);
        m.y = fmaxf(fmaxf(fmaxf(acc[0][o].y, acc[1][o].y), fmaxf(acc[2][o].y, acc[3][o].y)), 0.f);
        *(float2*)&g_h1[((o * 14 + oh) * 14 + ow) * BATCH + b] = m;
    }
}

// ---------------------------------------------------------------------------
// Kernel B: untied conv2 + relu + maxpool. 2 batch items per thread (float2).
// grid (25 positions, 2 channel groups of 8, 4 batch chunks of 256), block 128
// ---------------------------------------------------------------------------
__global__ void __launch_bounds__(128) k_conv2(const float* __restrict__ w2,
                                               const float* __restrict__ b2) {
    __shared__ float w_s[4800];   // [s][ol][c][25]
    __shared__ float bias_s[32];  // [s][ol]
    int pos = blockIdx.x;
    int oh = pos / 5, ow = pos % 5;
    int og = blockIdx.y;
    int tid = threadIdx.x;

    for (int l = tid; l < 4800; l += 128) {
        int s = l / 1200, r = l % 1200;
        int ol = r / 150, r2 = r % 150;
        int c = r2 / 25, kk = r2 % 25;
        int o = og * 8 + ol;
        int y = 2 * oh + (s >> 1), x2 = 2 * ow + (s & 1);
        w_s[l] = w2[(((o * 6 + c) * 10 + y) * 10 + x2) * 25 + kk];
    }
    if (tid < 32) {
        int s = tid / 8, ol = tid % 8;
        int o = og * 8 + ol;
        int y = 2 * oh + (s >> 1), x2 = 2 * ow + (s & 1);
        bias_s[tid] = b2[(o * 10 + y) * 10 + x2];
    }
    __syncthreads();

    int b = blockIdx.z * 256 + tid * 2;
    float2 acc[4][8];
#pragma unroll
    for (int s = 0; s < 4; s++)
#pragma unroll
        for (int ol = 0; ol < 8; ol++) {
            float bb = bias_s[s * 8 + ol];
            acc[s][ol] = make_float2(bb, bb);
        }

    for (int c = 0; c < 6; c++) {
        float2 p[6][6];
#pragma unroll
        for (int iy = 0; iy < 6; iy++)
#pragma unroll
            for (int ix = 0; ix < 6; ix++)
                p[iy][ix] = *(const float2*)&g_h1[((c * 14 + 2 * oh + iy) * 14 + 2 * ow + ix) * BATCH + b];
#pragma unroll
        for (int s = 0; s < 4; s++) {
            int sy = s >> 1, sx = s & 1;
#pragma unroll
            for (int ol = 0; ol < 8; ol++) {
                const float* wp = &w_s[(s * 8 + ol) * 150 + c * 25];
                float2 a = acc[s][ol];
#pragma unroll
                for (int ky = 0; ky < 5; ky++)
#pragma unroll
                    for (int kx = 0; kx < 5; kx++) {
                        float wv = wp[ky * 5 + kx];
                        a.x += p[sy + ky][sx + kx].x * wv;
                        a.y += p[sy + ky][sx + kx].y * wv;
                    }
                acc[s][ol] = a;
            }
        }
    }
#pragma unroll
    for (int ol = 0; ol < 8; ol++) {
        int o = og * 8 + ol;
        float2 m;
        m.x = fmaxf(fmaxf(fmaxf(acc[0][ol].x, acc[1][ol].x), fmaxf(acc[2][ol].x, acc[3][ol].x)), 0.f);
        m.y = fmaxf(fmaxf(fmaxf(acc[0][ol].y, acc[1][ol].y), fmaxf(acc[2][ol].y, acc[3][ol].y)), 0.f);
        *(float2*)&g_h2[((o * 5 + oh) * 5 + ow) * BATCH + b] = m;
    }
}

// ---------------------------------------------------------------------------
// Kernel C: conv3 GEMM out(1024,120) = h2(1024,400) @ w3(120,400)^T, relu.
// block 256 = 32 batch-lanes (x4 items) x 8 outputs; grid (8 batch tiles, 15 og)
// A read straight from gmem as float4 (coalesced, L2-resident), W from SMEM.
// ---------------------------------------------------------------------------
__global__ void __launch_bounds__(256) k_conv3(const float* __restrict__ w3,
                                               const float* __restrict__ b3) {
    __shared__ float W_s[8 * 400];
    int tid = threadIdx.x;
    int og = blockIdx.y;

    for (int l = tid; l < 3200; l += 256)
        W_s[l] = w3[og * 3200 + l];
    __syncthreads();

    int blane = tid & 31, olocal = tid >> 5;
    int o = og * 8 + olocal;
    int b = blockIdx.x * 128 + blane * 4;

    float bv = b3[o];
    float acc0 = bv, acc1 = bv, acc2 = bv, acc3 = bv;

    const float* wrow = &W_s[olocal * 400];
#pragma unroll 8
    for (int k = 0; k < 400; k++) {
        float4 a = *(const float4*)&g_h2[k * BATCH + b];
        float wv = wrow[k];
        acc0 += a.x * wv;
        acc1 += a.y * wv;
        acc2 += a.z * wv;
        acc3 += a.w * wv;
    }
    g_h3[(b + 0) * 120 + o] = fmaxf(acc0, 0.f);
    g_h3[(b + 1) * 120 + o] = fmaxf(acc1, 0.f);
    g_h3[(b + 2) * 120 + o] = fmaxf(acc2, 0.f);
    g_h3[(b + 3) * 120 + o] = fmaxf(acc3, 0.f);
}

// ---------------------------------------------------------------------------
// Kernel D: fused FC2 (120->84, relu) + FC3 (84->10). One warp per batch item.
// ---------------------------------------------------------------------------
__global__ void __launch_bounds__(256) k_fc(const float* __restrict__ fc2_w,
                                            const float* __restrict__ fc2_b,
                                            const float* __restrict__ fc3_w,
                                            const float* __restrict__ fc3_b,
                                            float* __restrict__ out) {
    __shared__ float w2_s[84 * 121];
    __shared__ float h_s[8][120];
    __shared__ float h84_s[8][84];
    int tid = threadIdx.x;

    for (int l = tid; l < 84 * 120; l += 256) {
        int r = l / 120, c = l % 120;
        w2_s[r * 121 + c] = fc2_w[l];
    }
    __syncthreads();

    int w = tid >> 5, lane = tid & 31;
    int b = blockIdx.x * 8 + w;

#pragma unroll
    for (int m = 0; m < 4; m++) {
        int k = lane + 32 * m;
        if (k < 120) h_s[w][k] = g_h3[b * 120 + k];
    }
    __syncwarp();

#pragma unroll
    for (int m = 0; m < 3; m++) {
        int jj = lane + 32 * m;
        if (jj < 84) {
            float a = fc2_b[jj];
#pragma unroll
            for (int k = 0; k < 120; k++)
                a += h_s[w][k] * w2_s[jj * 121 + k];
            h84_s[w][jj] = fmaxf(a, 0.f);
        }
    }
    __syncwarp();

    if (lane < 10) {
        float a = fc3_b[lane];
#pragma unroll
        for (int k = 0; k < 84; k++)
            a += h84_s[w][k] * fc3_w[lane * 84 + k];
        out[b * 10 + lane] = a;
    }
}

// ---------------------------------------------------------------------------
extern "C" void kernel_launch(void* const* d_in, const int* in_sizes, int n_in,
                              void* d_out, int out_size) {
    const float* x    = (const float*)d_in[0];
    const float* w1   = (const float*)d_in[1];
    const float* b1   = (const float*)d_in[2];
    const float* w2   = (const float*)d_in[3];
    const float* b2   = (const float*)d_in[4];
    const float* w3   = (const float*)d_in[5];
    const float* b3   = (const float*)d_in[6];
    const float* fc2w = (const float*)d_in[7];
    const float* fc2b = (const float*)d_in[8];
    const float* fc3w = (const float*)d_in[9];
    const float* fc3b = (const float*)d_in[10];
    float* out = (float*)d_out;

    k_transpose<<<dim3(96, 32), dim3(32, 8)>>>(x);
    k_conv1<<<dim3(196, 4), 128>>>(w1, b1);
    k_conv2<<<dim3(25, 2, 4), 128>>>(w2, b2);
    k_conv3<<<dim3(8, 15), 256>>>(w3, b3);
    k_fc<<<128, 256>>>(fc2w, fc2b, fc3w, fc3b, out);
}

// round 3
// speedup vs baseline: 1.3859x; 1.3859x over previous
#include <cuda_runtime.h>

#define BATCH 1024

__device__ float g_xT[3 * 32 * 32 * BATCH];   // (C,H,W,B)
__device__ float g_h1[6 * 14 * 14 * BATCH];   // (O1,Ho,Wo,B)
__device__ float g_h2[16 * 25 * BATCH];       // (O2,5,5,B)
__device__ float g_h3[BATCH * 120];           // (B,120)

// ---------------------------------------------------------------------------
// Kernel 0: transpose x (B, 3072) -> xT (3072, B)
// ---------------------------------------------------------------------------
__global__ void k_transpose(const float* __restrict__ x) {
    __shared__ float tile[32][33];
    int f0 = blockIdx.x * 32;
    int b0 = blockIdx.y * 32;
    int tx = threadIdx.x, ty = threadIdx.y;
#pragma unroll
    for (int i = 0; i < 4; i++)
        tile[ty + i * 8][tx] = x[(b0 + ty + i * 8) * 3072 + f0 + tx];
    __syncthreads();
#pragma unroll
    for (int i = 0; i < 4; i++)
        g_xT[(f0 + ty + i * 8) * BATCH + b0 + tx] = tile[tx][ty + i * 8];
}

// ---------------------------------------------------------------------------
// Kernel A: untied conv1 + relu + maxpool. 2 batch items per thread (float2).
// ---------------------------------------------------------------------------
__global__ void __launch_bounds__(128) k_conv1(const float* __restrict__ w1,
                                               const float* __restrict__ b1) {
    __shared__ float w_s[1800];   // [s][o][c][25]
    __shared__ float bias_s[24];  // [s][o]
    int pos = blockIdx.x;
    int oh = pos / 14, ow = pos % 14;
    int tid = threadIdx.x;

    for (int l = tid; l < 1800; l += 128) {
        int s = l / 450, r = l % 450;
        int o = r / 75, r2 = r % 75;
        int c = r2 / 25, kk = r2 % 25;
        int y = 2 * oh + (s >> 1), x2 = 2 * ow + (s & 1);
        w_s[l] = w1[(((o * 3 + c) * 28 + y) * 28 + x2) * 25 + kk];
    }
    if (tid < 24) {
        int s = tid / 6, o = tid % 6;
        int y = 2 * oh + (s >> 1), x2 = 2 * ow + (s & 1);
        bias_s[tid] = b1[(o * 28 + y) * 28 + x2];
    }
    __syncthreads();

    int b = blockIdx.y * 256 + tid * 2;
    float2 acc[4][6];
#pragma unroll
    for (int s = 0; s < 4; s++)
#pragma unroll
        for (int o = 0; o < 6; o++) {
            float bb = bias_s[s * 6 + o];
            acc[s][o] = make_float2(bb, bb);
        }

    for (int c = 0; c < 3; c++) {
        float2 p[6][6];
#pragma unroll
        for (int iy = 0; iy < 6; iy++)
#pragma unroll
            for (int ix = 0; ix < 6; ix++)
                p[iy][ix] = *(const float2*)&g_xT[((c * 32 + 2 * oh + iy) * 32 + 2 * ow + ix) * BATCH + b];
#pragma unroll
        for (int s = 0; s < 4; s++) {
            int sy = s >> 1, sx = s & 1;
#pragma unroll
            for (int o = 0; o < 6; o++) {
                const float* wp = &w_s[(s * 6 + o) * 75 + c * 25];
                float2 a = acc[s][o];
#pragma unroll
                for (int ky = 0; ky < 5; ky++)
#pragma unroll
                    for (int kx = 0; kx < 5; kx++) {
                        float wv = wp[ky * 5 + kx];
                        a.x += p[sy + ky][sx + kx].x * wv;
                        a.y += p[sy + ky][sx + kx].y * wv;
                    }
                acc[s][o] = a;
            }
        }
    }
#pragma unroll
    for (int o = 0; o < 6; o++) {
        float2 m;
        m.x = fmaxf(fmaxf(fmaxf(acc[0][o].x, acc[1][o].x), fmaxf(acc[2][o].x, acc[3][o].x)), 0.f);
        m.y = fmaxf(fmaxf(fmaxf(acc[0][o].y, acc[1][o].y), fmaxf(acc[2][o].y, acc[3][o].y)), 0.f);
        *(float2*)&g_h1[((o * 14 + oh) * 14 + ow) * BATCH + b] = m;
    }
}

// ---------------------------------------------------------------------------
// Kernel B: untied conv2 + relu + maxpool. 2 batch items per thread (float2).
// ---------------------------------------------------------------------------
__global__ void __launch_bounds__(128) k_conv2(const float* __restrict__ w2,
                                               const float* __restrict__ b2) {
    __shared__ float w_s[4800];   // [s][ol][c][25]
    __shared__ float bias_s[32];  // [s][ol]
    int pos = blockIdx.x;
    int oh = pos / 5, ow = pos % 5;
    int og = blockIdx.y;
    int tid = threadIdx.x;

    for (int l = tid; l < 4800; l += 128) {
        int s = l / 1200, r = l % 1200;
        int ol = r / 150, r2 = r % 150;
        int c = r2 / 25, kk = r2 % 25;
        int o = og * 8 + ol;
        int y = 2 * oh + (s >> 1), x2 = 2 * ow + (s & 1);
        w_s[l] = w2[(((o * 6 + c) * 10 + y) * 10 + x2) * 25 + kk];
    }
    if (tid < 32) {
        int s = tid / 8, ol = tid % 8;
        int o = og * 8 + ol;
        int y = 2 * oh + (s >> 1), x2 = 2 * ow + (s & 1);
        bias_s[tid] = b2[(o * 10 + y) * 10 + x2];
    }
    __syncthreads();

    int b = blockIdx.z * 256 + tid * 2;
    float2 acc[4][8];
#pragma unroll
    for (int s = 0; s < 4; s++)
#pragma unroll
        for (int ol = 0; ol < 8; ol++) {
            float bb = bias_s[s * 8 + ol];
            acc[s][ol] = make_float2(bb, bb);
        }

    for (int c = 0; c < 6; c++) {
        float2 p[6][6];
#pragma unroll
        for (int iy = 0; iy < 6; iy++)
#pragma unroll
            for (int ix = 0; ix < 6; ix++)
                p[iy][ix] = *(const float2*)&g_h1[((c * 14 + 2 * oh + iy) * 14 + 2 * ow + ix) * BATCH + b];
#pragma unroll
        for (int s = 0; s < 4; s++) {
            int sy = s >> 1, sx = s & 1;
#pragma unroll
            for (int ol = 0; ol < 8; ol++) {
                const float* wp = &w_s[(s * 8 + ol) * 150 + c * 25];
                float2 a = acc[s][ol];
#pragma unroll
                for (int ky = 0; ky < 5; ky++)
#pragma unroll
                    for (int kx = 0; kx < 5; kx++) {
                        float wv = wp[ky * 5 + kx];
                        a.x += p[sy + ky][sx + kx].x * wv;
                        a.y += p[sy + ky][sx + kx].y * wv;
                    }
                acc[s][ol] = a;
            }
        }
    }
#pragma unroll
    for (int ol = 0; ol < 8; ol++) {
        int o = og * 8 + ol;
        float2 m;
        m.x = fmaxf(fmaxf(fmaxf(acc[0][ol].x, acc[1][ol].x), fmaxf(acc[2][ol].x, acc[3][ol].x)), 0.f);
        m.y = fmaxf(fmaxf(fmaxf(acc[0][ol].y, acc[1][ol].y), fmaxf(acc[2][ol].y, acc[3][ol].y)), 0.f);
        *(float2*)&g_h2[((o * 5 + oh) * 5 + ow) * BATCH + b] = m;
    }
}

// ---------------------------------------------------------------------------
// Kernel C: conv3 GEMM out(1024,120) = h2(1024,400) @ w3(120,400)^T, relu.
// SMEM-staged A (cooperative, high-MLP load) + broadcast weights.
// Block 128 = 32 batch-lanes x 4 out-pairs; thread = 4 batch x 2 outs.
// Grid (8 batch-tiles of 128, 15 out-groups of 8) = 120 blocks.
// ---------------------------------------------------------------------------
__global__ void __launch_bounds__(128) k_conv3(const float* __restrict__ w3,
                                               const float* __restrict__ b3) {
    __shared__ float A_s[100 * 128];  // K-chunk x batch  (51.2 KB)
    __shared__ float W_s[8 * 400];    // [ol][k]          (12.8 KB)
    int tid = threadIdx.x;
    int og = blockIdx.y;
    int b0 = blockIdx.x * 128;

    // stage all 8 output rows of W (vectorized)
    for (int l = tid; l < 800; l += 128)
        *(float4*)&W_s[l * 4] = *(const float4*)&w3[og * 3200 + l * 4];

    int blane = tid & 31, ogl = tid >> 5;          // ogl 0..3
    int o0 = og * 8 + ogl * 2;
    float bv0 = b3[o0], bv1 = b3[o0 + 1];
    float4 acc0 = make_float4(bv0, bv0, bv0, bv0);
    float4 acc1 = make_float4(bv1, bv1, bv1, bv1);

    const float* w0p = &W_s[(ogl * 2) * 400];
    const float* w1p = &W_s[(ogl * 2 + 1) * 400];

    for (int kc = 0; kc < 400; kc += 100) {
        __syncthreads();
        // cooperative stage: 25 float4 LDG per thread, back-to-back (high MLP)
        for (int l = tid; l < 3200; l += 128) {
            int k = l >> 5;
            int c4 = (l & 31) * 4;
            *(float4*)&A_s[k * 128 + c4] =
                *(const float4*)&g_h2[(kc + k) * BATCH + b0 + c4];
        }
        __syncthreads();
#pragma unroll 10
        for (int k = 0; k < 100; k++) {
            float4 a = *(const float4*)&A_s[k * 128 + blane * 4];
            float w0 = w0p[kc + k];
            float w1 = w1p[kc + k];
            acc0.x += a.x * w0; acc0.y += a.y * w0;
            acc0.z += a.z * w0; acc0.w += a.w * w0;
            acc1.x += a.x * w1; acc1.y += a.y * w1;
            acc1.z += a.z * w1; acc1.w += a.w * w1;
        }
    }

    int b = b0 + blane * 4;
    g_h3[(b + 0) * 120 + o0] = fmaxf(acc0.x, 0.f);
    g_h3[(b + 1) * 120 + o0] = fmaxf(acc0.y, 0.f);
    g_h3[(b + 2) * 120 + o0] = fmaxf(acc0.z, 0.f);
    g_h3[(b + 3) * 120 + o0] = fmaxf(acc0.w, 0.f);
    g_h3[(b + 0) * 120 + o0 + 1] = fmaxf(acc1.x, 0.f);
    g_h3[(b + 1) * 120 + o0 + 1] = fmaxf(acc1.y, 0.f);
    g_h3[(b + 2) * 120 + o0 + 1] = fmaxf(acc1.z, 0.f);
    g_h3[(b + 3) * 120 + o0 + 1] = fmaxf(acc1.w, 0.f);
}

// ---------------------------------------------------------------------------
// Kernel D: fused FC2 (120->84, relu) + FC3 (84->10). One warp per batch item.
// ---------------------------------------------------------------------------
__global__ void __launch_bounds__(256) k_fc(const float* __restrict__ fc2_w,
                                            const float* __restrict__ fc2_b,
                                            const float* __restrict__ fc3_w,
                                            const float* __restrict__ fc3_b,
                                            float* __restrict__ out) {
    __shared__ float w2_s[84 * 121];
    __shared__ float h_s[8][120];
    __shared__ float h84_s[8][84];
    int tid = threadIdx.x;

    for (int l = tid; l < 84 * 120; l += 256) {
        int r = l / 120, c = l % 120;
        w2_s[r * 121 + c] = fc2_w[l];
    }
    __syncthreads();

    int w = tid >> 5, lane = tid & 31;
    int b = blockIdx.x * 8 + w;

#pragma unroll
    for (int m = 0; m < 4; m++) {
        int k = lane + 32 * m;
        if (k < 120) h_s[w][k] = g_h3[b * 120 + k];
    }
    __syncwarp();

#pragma unroll
    for (int m = 0; m < 3; m++) {
        int jj = lane + 32 * m;
        if (jj < 84) {
            float a = fc2_b[jj];
#pragma unroll
            for (int k = 0; k < 120; k++)
                a += h_s[w][k] * w2_s[jj * 121 + k];
            h84_s[w][jj] = fmaxf(a, 0.f);
        }
    }
    __syncwarp();

    if (lane < 10) {
        float a = fc3_b[lane];
#pragma unroll
        for (int k = 0; k < 84; k++)
            a += h84_s[w][k] * fc3_w[lane * 84 + k];
        out[b * 10 + lane] = a;
    }
}

// ---------------------------------------------------------------------------
extern "C" void kernel_launch(void* const* d_in, const int* in_sizes, int n_in,
                              void* d_out, int out_size) {
    const float* x    = (const float*)d_in[0];
    const float* w1   = (const float*)d_in[1];
    const float* b1   = (const float*)d_in[2];
    const float* w2   = (const float*)d_in[3];
    const float* b2   = (const float*)d_in[4];
    const float* w3   = (const float*)d_in[5];
    const float* b3   = (const float*)d_in[6];
    const float* fc2w = (const float*)d_in[7];
    const float* fc2b = (const float*)d_in[8];
    const float* fc3w = (const float*)d_in[9];
    const float* fc3b = (const float*)d_in[10];
    float* out = (float*)d_out;

    k_transpose<<<dim3(96, 32), dim3(32, 8)>>>(x);
    k_conv1<<<dim3(196, 4), 128>>>(w1, b1);
    k_conv2<<<dim3(25, 2, 4), 128>>>(w2, b2);
    k_conv3<<<dim3(8, 15), 128>>>(w3, b3);
    k_fc<<<128, 256>>>(fc2w, fc2b, fc3w, fc3b, out);
}

// round 4
// speedup vs baseline: 1.4714x; 1.0617x over previous
#include <cuda_runtime.h>
#include <cstdint>

#define BATCH 1024

__device__ float g_xT[3 * 32 * 32 * BATCH];    // (C,H,W,B)
__device__ float g_h1[6 * 14 * 14 * BATCH];    // (O1,Ho,Wo,B)
__device__ float g_h2[16 * 25 * BATCH];        // (O2,5,5,B)
__device__ float g_h3p[4 * BATCH * 120];       // split-K partials of conv3

typedef unsigned long long ull;

__device__ __forceinline__ ull pack2(float x, float y) {
    ull u;
    asm("mov.b64 %0, {%1, %2};" : "=l"(u) : "r"(__float_as_uint(x)), "r"(__float_as_uint(y)));
    return u;
}
__device__ __forceinline__ float2 unpack2(ull u) {
    uint32_t lo, hi;
    asm("mov.b64 {%0, %1}, %2;" : "=r"(lo), "=r"(hi) : "l"(u));
    return make_float2(__uint_as_float(lo), __uint_as_float(hi));
}
__device__ __forceinline__ void ffma2(ull& d, ull a, ull b) {
    asm("fma.rn.f32x2 %0, %1, %2, %0;" : "+l"(d) : "l"(a), "l"(b));
}

// ---------------------------------------------------------------------------
// Kernel 0: transpose x (B, 3072) -> xT (3072, B)
// ---------------------------------------------------------------------------
__global__ void k_transpose(const float* __restrict__ x) {
    __shared__ float tile[32][33];
    int f0 = blockIdx.x * 32;
    int b0 = blockIdx.y * 32;
    int tx = threadIdx.x, ty = threadIdx.y;
#pragma unroll
    for (int i = 0; i < 4; i++)
        tile[ty + i * 8][tx] = x[(b0 + ty + i * 8) * 3072 + f0 + tx];
    __syncthreads();
#pragma unroll
    for (int i = 0; i < 4; i++)
        g_xT[(f0 + ty + i * 8) * BATCH + b0 + tx] = tile[tx][ty + i * 8];
}

// ---------------------------------------------------------------------------
// Kernel A: untied conv1 + relu + maxpool, packed f32x2 (2 batch / thread).
// grid (196 positions, 4 batch chunks of 256), block 128.
// ---------------------------------------------------------------------------
__global__ void __launch_bounds__(128) k_conv1(const float* __restrict__ w1,
                                               const float* __restrict__ b1) {
    __shared__ ull w_s[1800];     // [s][o][c][25], each weight duplicated {w,w}
    __shared__ float bias_s[24];
    int pos = blockIdx.x;
    int oh = pos / 14, ow = pos % 14;
    int tid = threadIdx.x;

    for (int l = tid; l < 1800; l += 128) {
        int s = l / 450, r = l % 450;
        int o = r / 75, r2 = r % 75;
        int c = r2 / 25, kk = r2 % 25;
        int y = 2 * oh + (s >> 1), x2 = 2 * ow + (s & 1);
        float v = w1[(((o * 3 + c) * 28 + y) * 28 + x2) * 25 + kk];
        w_s[l] = pack2(v, v);
    }
    if (tid < 24) {
        int s = tid / 6, o = tid % 6;
        int y = 2 * oh + (s >> 1), x2 = 2 * ow + (s & 1);
        bias_s[tid] = b1[(o * 28 + y) * 28 + x2];
    }
    __syncthreads();

    int b = blockIdx.y * 256 + tid * 2;
    ull acc[4][6];
#pragma unroll
    for (int s = 0; s < 4; s++)
#pragma unroll
        for (int o = 0; o < 6; o++) {
            float bb = bias_s[s * 6 + o];
            acc[s][o] = pack2(bb, bb);
        }

    for (int c = 0; c < 3; c++) {
        ull p[6][6];
#pragma unroll
        for (int iy = 0; iy < 6; iy++)
#pragma unroll
            for (int ix = 0; ix < 6; ix++)
                p[iy][ix] = *(const ull*)&g_xT[((c * 32 + 2 * oh + iy) * 32 + 2 * ow + ix) * BATCH + b];
#pragma unroll
        for (int s = 0; s < 4; s++) {
            int sy = s >> 1, sx = s & 1;
#pragma unroll
            for (int o = 0; o < 6; o++) {
                const ull* wp = &w_s[(s * 6 + o) * 75 + c * 25];
#pragma unroll
                for (int ky = 0; ky < 5; ky++)
#pragma unroll
                    for (int kx = 0; kx < 5; kx++)
                        ffma2(acc[s][o], p[sy + ky][sx + kx], wp[ky * 5 + kx]);
            }
        }
    }
#pragma unroll
    for (int o = 0; o < 6; o++) {
        float2 a0 = unpack2(acc[0][o]), a1 = unpack2(acc[1][o]);
        float2 a2 = unpack2(acc[2][o]), a3 = unpack2(acc[3][o]);
        float2 m;
        m.x = fmaxf(fmaxf(fmaxf(a0.x, a1.x), fmaxf(a2.x, a3.x)), 0.f);
        m.y = fmaxf(fmaxf(fmaxf(a0.y, a1.y), fmaxf(a2.y, a3.y)), 0.f);
        *(float2*)&g_h1[((o * 14 + oh) * 14 + ow) * BATCH + b] = m;
    }
}

// ---------------------------------------------------------------------------
// Kernel B: untied conv2 + relu + maxpool, packed f32x2 (2 batch / thread).
// grid (25 positions, 4 channel groups of 4, 4 batch chunks of 256), block 128.
// ---------------------------------------------------------------------------
__global__ void __launch_bounds__(128) k_conv2(const float* __restrict__ w2,
                                               const float* __restrict__ b2) {
    __shared__ ull w_s[2400];     // [s][ol][c][25] duplicated
    __shared__ float bias_s[16];
    int pos = blockIdx.x;
    int oh = pos / 5, ow = pos % 5;
    int og = blockIdx.y;
    int tid = threadIdx.x;

    for (int l = tid; l < 2400; l += 128) {
        int s = l / 600, r = l % 600;
        int ol = r / 150, r2 = r % 150;
        int c = r2 / 25, kk = r2 % 25;
        int o = og * 4 + ol;
        int y = 2 * oh + (s >> 1), x2 = 2 * ow + (s & 1);
        float v = w2[(((o * 6 + c) * 10 + y) * 10 + x2) * 25 + kk];
        w_s[l] = pack2(v, v);
    }
    if (tid < 16) {
        int s = tid / 4, ol = tid % 4;
        int o = og * 4 + ol;
        int y = 2 * oh + (s >> 1), x2 = 2 * ow + (s & 1);
        bias_s[tid] = b2[(o * 10 + y) * 10 + x2];
    }
    __syncthreads();

    int b = blockIdx.z * 256 + tid * 2;
    ull acc[4][4];
#pragma unroll
    for (int s = 0; s < 4; s++)
#pragma unroll
        for (int ol = 0; ol < 4; ol++) {
            float bb = bias_s[s * 4 + ol];
            acc[s][ol] = pack2(bb, bb);
        }

    for (int c = 0; c < 6; c++) {
        ull p[6][6];
#pragma unroll
        for (int iy = 0; iy < 6; iy++)
#pragma unroll
            for (int ix = 0; ix < 6; ix++)
                p[iy][ix] = *(const ull*)&g_h1[((c * 14 + 2 * oh + iy) * 14 + 2 * ow + ix) * BATCH + b];
#pragma unroll
        for (int s = 0; s < 4; s++) {
            int sy = s >> 1, sx = s & 1;
#pragma unroll
            for (int ol = 0; ol < 4; ol++) {
                const ull* wp = &w_s[(s * 4 + ol) * 150 + c * 25];
#pragma unroll
                for (int ky = 0; ky < 5; ky++)
#pragma unroll
                    for (int kx = 0; kx < 5; kx++)
                        ffma2(acc[s][ol], p[sy + ky][sx + kx], wp[ky * 5 + kx]);
            }
        }
    }
#pragma unroll
    for (int ol = 0; ol < 4; ol++) {
        int o = og * 4 + ol;
        float2 a0 = unpack2(acc[0][ol]), a1 = unpack2(acc[1][ol]);
        float2 a2 = unpack2(acc[2][ol]), a3 = unpack2(acc[3][ol]);
        float2 m;
        m.x = fmaxf(fmaxf(fmaxf(a0.x, a1.x), fmaxf(a2.x, a3.x)), 0.f);
        m.y = fmaxf(fmaxf(fmaxf(a0.y, a1.y), fmaxf(a2.y, a3.y)), 0.f);
        *(float2*)&g_h2[((o * 5 + oh) * 5 + ow) * BATCH + b] = m;
    }
}

// ---------------------------------------------------------------------------
// Kernel C: conv3 GEMM partials, split-K=4.
// grid (8 batch tiles of 128, 15 out-groups of 8, 4 k-splits of 100), block 128.
// Thread = 4 batch (LDS128) x 2 outs. No bias/relu here (done in k_fc).
// ---------------------------------------------------------------------------
__global__ void __launch_bounds__(128) k_conv3(const float* __restrict__ w3) {
    __shared__ float A_s[100 * 128];  // 51.2 KB
    __shared__ float W_s[8 * 100];    //  3.2 KB
    int tid = threadIdx.x;
    int og = blockIdx.y;
    int b0 = blockIdx.x * 128;
    int kc = blockIdx.z * 100;

    for (int l = tid; l < 800; l += 128) {
        int ol = l / 100, k = l % 100;
        W_s[l] = w3[(og * 8 + ol) * 400 + kc + k];
    }
    for (int l = tid; l < 3200; l += 128) {
        int k = l >> 5;
        int c4 = (l & 31) * 4;
        *(float4*)&A_s[k * 128 + c4] =
            *(const float4*)&g_h2[(kc + k) * BATCH + b0 + c4];
    }
    __syncthreads();

    int blane = tid & 31, ogl = tid >> 5;
    int o0 = og * 8 + ogl * 2;
    float4 acc0 = make_float4(0.f, 0.f, 0.f, 0.f);
    float4 acc1 = make_float4(0.f, 0.f, 0.f, 0.f);
    const float* w0p = &W_s[(ogl * 2) * 100];
    const float* w1p = &W_s[(ogl * 2 + 1) * 100];

#pragma unroll 10
    for (int k = 0; k < 100; k++) {
        float4 a = *(const float4*)&A_s[k * 128 + blane * 4];
        float w0 = w0p[k];
        float w1 = w1p[k];
        acc0.x += a.x * w0; acc0.y += a.y * w0;
        acc0.z += a.z * w0; acc0.w += a.w * w0;
        acc1.x += a.x * w1; acc1.y += a.y * w1;
        acc1.z += a.z * w1; acc1.w += a.w * w1;
    }

    int b = blockIdx.z * BATCH + b0 + blane * 4;
    g_h3p[(b + 0) * 120 + o0] = acc0.x;
    g_h3p[(b + 1) * 120 + o0] = acc0.y;
    g_h3p[(b + 2) * 120 + o0] = acc0.z;
    g_h3p[(b + 3) * 120 + o0] = acc0.w;
    g_h3p[(b + 0) * 120 + o0 + 1] = acc1.x;
    g_h3p[(b + 1) * 120 + o0 + 1] = acc1.y;
    g_h3p[(b + 2) * 120 + o0 + 1] = acc1.z;
    g_h3p[(b + 3) * 120 + o0 + 1] = acc1.w;
}

// ---------------------------------------------------------------------------
// Kernel D: reduce conv3 partials + bias + relu, then FC2(relu) + FC3.
// One warp per batch item; grid 128 x block 256.
// ---------------------------------------------------------------------------
__global__ void __launch_bounds__(256) k_fc(const float* __restrict__ b3,
                                            const float* __restrict__ fc2_w,
                                            const float* __restrict__ fc2_b,
                                            const float* __restrict__ fc3_w,
                                            const float* __restrict__ fc3_b,
                                            float* __restrict__ out) {
    __shared__ float w2_s[84 * 121];
    __shared__ float h_s[8][120];
    __shared__ float h84_s[8][84];
    int tid = threadIdx.x;

    for (int l = tid; l < 84 * 120; l += 256) {
        int r = l / 120, c = l % 120;
        w2_s[r * 121 + c] = fc2_w[l];
    }
    __syncthreads();

    int w = tid >> 5, lane = tid & 31;
    int b = blockIdx.x * 8 + w;

#pragma unroll
    for (int m = 0; m < 4; m++) {
        int k = lane + 32 * m;
        if (k < 120) {
            float s = b3[k];
#pragma unroll
            for (int z = 0; z < 4; z++)
                s += g_h3p[(z * BATCH + b) * 120 + k];
            h_s[w][k] = fmaxf(s, 0.f);
        }
    }
    __syncwarp();

#pragma unroll
    for (int m = 0; m < 3; m++) {
        int jj = lane + 32 * m;
        if (jj < 84) {
            float a = fc2_b[jj];
#pragma unroll
            for (int k = 0; k < 120; k++)
                a += h_s[w][k] * w2_s[jj * 121 + k];
            h84_s[w][jj] = fmaxf(a, 0.f);
        }
    }
    __syncwarp();

    if (lane < 10) {
        float a = fc3_b[lane];
#pragma unroll
        for (int k = 0; k < 84; k++)
            a += h84_s[w][k] * fc3_w[lane * 84 + k];
        out[b * 10 + lane] = a;
    }
}

// ---------------------------------------------------------------------------
extern "C" void kernel_launch(void* const* d_in, const int* in_sizes, int n_in,
                              void* d_out, int out_size) {
    const float* x    = (const float*)d_in[0];
    const float* w1   = (const float*)d_in[1];
    const float* b1   = (const float*)d_in[2];
    const float* w2   = (const float*)d_in[3];
    const float* b2   = (const float*)d_in[4];
    const float* w3   = (const float*)d_in[5];
    const float* b3   = (const float*)d_in[6];
    const float* fc2w = (const float*)d_in[7];
    const float* fc2b = (const float*)d_in[8];
    const float* fc3w = (const float*)d_in[9];
    const float* fc3b = (const float*)d_in[10];
    float* out = (float*)d_out;

    k_transpose<<<dim3(96, 32), dim3(32, 8)>>>(x);
    k_conv1<<<dim3(196, 4), 128>>>(w1, b1);
    k_conv2<<<dim3(25, 4, 4), 128>>>(w2, b2);
    k_conv3<<<dim3(8, 15, 4), 128>>>(w3);
    k_fc<<<128, 256>>>(b3, fc2w, fc2b, fc3w, fc3b, out);
}

// round 5
// speedup vs baseline: 1.6114x; 1.0952x over previous
#include <cuda_runtime.h>
#include <cuda_pipeline.h>
#include <cstdint>

#define BATCH 1024

__device__ float g_xT[3 * 32 * 32 * BATCH];    // (C,H,W,B)
__device__ float g_h1[6 * 14 * 14 * BATCH];    // (O1,Ho,Wo,B)
__device__ float g_h2[16 * 25 * BATCH];        // (O2,5,5,B)
__device__ float g_h3p[4 * BATCH * 120];       // split-K partials of conv3

typedef unsigned long long ull;

__device__ __forceinline__ ull pack2(float x, float y) {
    ull u;
    asm("mov.b64 %0, {%1, %2};" : "=l"(u) : "r"(__float_as_uint(x)), "r"(__float_as_uint(y)));
    return u;
}
__device__ __forceinline__ float2 unpack2(ull u) {
    uint32_t lo, hi;
    asm("mov.b64 {%0, %1}, %2;" : "=r"(lo), "=r"(hi) : "l"(u));
    return make_float2(__uint_as_float(lo), __uint_as_float(hi));
}
__device__ __forceinline__ void ffma2(ull& d, ull a, ull b) {
    asm("fma.rn.f32x2 %0, %1, %2, %0;" : "+l"(d) : "l"(a), "l"(b));
}

// ---------------------------------------------------------------------------
// Kernel 0: transpose x (B, 3072) -> xT (3072, B)
// ---------------------------------------------------------------------------
__global__ void k_transpose(const float* __restrict__ x) {
    __shared__ float tile[32][33];
    int f0 = blockIdx.x * 32;
    int b0 = blockIdx.y * 32;
    int tx = threadIdx.x, ty = threadIdx.y;
#pragma unroll
    for (int i = 0; i < 4; i++)
        tile[ty + i * 8][tx] = x[(b0 + ty + i * 8) * 3072 + f0 + tx];
    __syncthreads();
#pragma unroll
    for (int i = 0; i < 4; i++)
        g_xT[(f0 + ty + i * 8) * BATCH + b0 + tx] = tile[tx][ty + i * 8];
}

// ---------------------------------------------------------------------------
// Kernel A: untied conv1 + relu + maxpool, packed f32x2, paired-weight LDS.128.
// Weight smem: [s][o][c] groups of 26 ull (25 weights {w,w} + 1 pad), 16B-aligned.
// grid (196 positions, 4 batch chunks of 256), block 128.
// ---------------------------------------------------------------------------
__global__ void __launch_bounds__(128) k_conv1(const float* __restrict__ w1,
                                               const float* __restrict__ b1) {
    __shared__ __align__(16) ull w_s[24 * 78];   // (s*6+o)*78 + c*26 + kk
    __shared__ float bias_s[24];
    int pos = blockIdx.x;
    int oh = pos / 14, ow = pos % 14;
    int tid = threadIdx.x;

    for (int l = tid; l < 24 * 78; l += 128) {
        int so = l / 78, r = l % 78;
        int c = r / 26, kk = r % 26;
        int s = so / 6, o = so % 6;
        float v = 0.f;
        if (kk < 25) {
            int y = 2 * oh + (s >> 1), x2 = 2 * ow + (s & 1);
            v = w1[(((o * 3 + c) * 28 + y) * 28 + x2) * 25 + kk];
        }
        w_s[l] = pack2(v, v);
    }
    if (tid < 24) {
        int s = tid / 6, o = tid % 6;
        int y = 2 * oh + (s >> 1), x2 = 2 * ow + (s & 1);
        bias_s[tid] = b1[(o * 28 + y) * 28 + x2];
    }
    __syncthreads();

    int b = blockIdx.y * 256 + tid * 2;
    ull acc[4][6];
#pragma unroll
    for (int s = 0; s < 4; s++)
#pragma unroll
        for (int o = 0; o < 6; o++) {
            float bb = bias_s[s * 6 + o];
            acc[s][o] = pack2(bb, bb);
        }

    for (int c = 0; c < 3; c++) {
        ull p[6][6];
#pragma unroll
        for (int iy = 0; iy < 6; iy++)
#pragma unroll
            for (int ix = 0; ix < 6; ix++)
                p[iy][ix] = *(const ull*)&g_xT[((c * 32 + 2 * oh + iy) * 32 + 2 * ow + ix) * BATCH + b];
#pragma unroll
        for (int s = 0; s < 4; s++) {
            int sy = s >> 1, sx = s & 1;
#pragma unroll
            for (int o = 0; o < 6; o++) {
                int base = (s * 6 + o) * 78 + c * 26;
                const ulonglong2* wp2 = reinterpret_cast<const ulonglong2*>(&w_s[base]);
#pragma unroll
                for (int kp = 0; kp < 12; kp++) {
                    ulonglong2 wv = wp2[kp];
                    ffma2(acc[s][o], p[sy + (2 * kp) / 5][sx + (2 * kp) % 5], wv.x);
                    ffma2(acc[s][o], p[sy + (2 * kp + 1) / 5][sx + (2 * kp + 1) % 5], wv.y);
                }
                ffma2(acc[s][o], p[sy + 4][sx + 4], w_s[base + 24]);
            }
        }
    }
#pragma unroll
    for (int o = 0; o < 6; o++) {
        float2 a0 = unpack2(acc[0][o]), a1 = unpack2(acc[1][o]);
        float2 a2 = unpack2(acc[2][o]), a3 = unpack2(acc[3][o]);
        float2 m;
        m.x = fmaxf(fmaxf(fmaxf(a0.x, a1.x), fmaxf(a2.x, a3.x)), 0.f);
        m.y = fmaxf(fmaxf(fmaxf(a0.y, a1.y), fmaxf(a2.y, a3.y)), 0.f);
        *(float2*)&g_h1[((o * 14 + oh) * 14 + ow) * BATCH + b] = m;
    }
}

// ---------------------------------------------------------------------------
// Kernel B: untied conv2 + relu + maxpool, same paired-weight scheme.
// grid (25 positions, 4 out-groups of 4, 4 batch chunks of 256), block 128.
// ---------------------------------------------------------------------------
__global__ void __launch_bounds__(128) k_conv2(const float* __restrict__ w2,
                                               const float* __restrict__ b2) {
    __shared__ __align__(16) ull w_s[16 * 156];  // (s*4+ol)*156 + c*26 + kk
    __shared__ float bias_s[16];
    int pos = blockIdx.x;
    int oh = pos / 5, ow = pos % 5;
    int og = blockIdx.y;
    int tid = threadIdx.x;

    for (int l = tid; l < 16 * 156; l += 128) {
        int sol = l / 156, r = l % 156;
        int c = r / 26, kk = r % 26;
        int s = sol / 4, ol = sol % 4;
        float v = 0.f;
        if (kk < 25) {
            int o = og * 4 + ol;
            int y = 2 * oh + (s >> 1), x2 = 2 * ow + (s & 1);
            v = w2[(((o * 6 + c) * 10 + y) * 10 + x2) * 25 + kk];
        }
        w_s[l] = pack2(v, v);
    }
    if (tid < 16) {
        int s = tid / 4, ol = tid % 4;
        int o = og * 4 + ol;
        int y = 2 * oh + (s >> 1), x2 = 2 * ow + (s & 1);
        bias_s[tid] = b2[(o * 10 + y) * 10 + x2];
    }
    __syncthreads();

    int b = blockIdx.z * 256 + tid * 2;
    ull acc[4][4];
#pragma unroll
    for (int s = 0; s < 4; s++)
#pragma unroll
        for (int ol = 0; ol < 4; ol++) {
            float bb = bias_s[s * 4 + ol];
            acc[s][ol] = pack2(bb, bb);
        }

    for (int c = 0; c < 6; c++) {
        ull p[6][6];
#pragma unroll
        for (int iy = 0; iy < 6; iy++)
#pragma unroll
            for (int ix = 0; ix < 6; ix++)
                p[iy][ix] = *(const ull*)&g_h1[((c * 14 + 2 * oh + iy) * 14 + 2 * ow + ix) * BATCH + b];
#pragma unroll
        for (int s = 0; s < 4; s++) {
            int sy = s >> 1, sx = s & 1;
#pragma unroll
            for (int ol = 0; ol < 4; ol++) {
                int base = (s * 4 + ol) * 156 + c * 26;
                const ulonglong2* wp2 = reinterpret_cast<const ulonglong2*>(&w_s[base]);
#pragma unroll
                for (int kp = 0; kp < 12; kp++) {
                    ulonglong2 wv = wp2[kp];
                    ffma2(acc[s][ol], p[sy + (2 * kp) / 5][sx + (2 * kp) % 5], wv.x);
                    ffma2(acc[s][ol], p[sy + (2 * kp + 1) / 5][sx + (2 * kp + 1) % 5], wv.y);
                }
                ffma2(acc[s][ol], p[sy + 4][sx + 4], w_s[base + 24]);
            }
        }
    }
#pragma unroll
    for (int ol = 0; ol < 4; ol++) {
        int o = og * 4 + ol;
        float2 a0 = unpack2(acc[0][ol]), a1 = unpack2(acc[1][ol]);
        float2 a2 = unpack2(acc[2][ol]), a3 = unpack2(acc[3][ol]);
        float2 m;
        m.x = fmaxf(fmaxf(fmaxf(a0.x, a1.x), fmaxf(a2.x, a3.x)), 0.f);
        m.y = fmaxf(fmaxf(fmaxf(a0.y, a1.y), fmaxf(a2.y, a3.y)), 0.f);
        *(float2*)&g_h2[((o * 5 + oh) * 5 + ow) * BATCH + b] = m;
    }
}

// ---------------------------------------------------------------------------
// Kernel C: conv3 GEMM partials, split-K=4, cp.async staging.
// grid (8 batch tiles of 128, 15 out-groups of 8, 4 k-splits of 100), block 128.
// Warp layout: wid&1 -> out quad, wid>>1 -> batch half. Thread = 2 batch x 4 outs.
// W staged k-major (W_s[k*8+ol]) so 4 weights = one LDS.128 broadcast.
// ---------------------------------------------------------------------------
__global__ void __launch_bounds__(128) k_conv3(const float* __restrict__ w3) {
    __shared__ __align__(16) float A_s[100 * 128];  // 51.2 KB
    __shared__ __align__(16) float W_s[100 * 8];    //  3.2 KB, k-major
    int tid = threadIdx.x;
    int og = blockIdx.y;
    int b0 = blockIdx.x * 128;
    int kc = blockIdx.z * 100;

    // async stage W (k-major transpose: 4B granules)
    for (int l = tid; l < 800; l += 128) {
        int k = l >> 3, ol = l & 7;
        __pipeline_memcpy_async(&W_s[l], &w3[(og * 8 + ol) * 400 + kc + k], 4);
    }
    // async stage A tile (16B granules, fully parallel)
    for (int l = tid; l < 3200; l += 128) {
        int k = l >> 5;
        int c4 = (l & 31) * 4;
        __pipeline_memcpy_async(&A_s[k * 128 + c4],
                                &g_h2[(kc + k) * BATCH + b0 + c4], 16);
    }
    __pipeline_commit();
    __pipeline_wait_prior(0);
    __syncthreads();

    int wid = tid >> 5, lane = tid & 31;
    int o4 = (wid & 1) * 4;          // out quad: 0 or 4
    int bb = (wid >> 1) * 64 + lane * 2;  // batch offset within tile

    float2 acc0 = make_float2(0.f, 0.f), acc1 = acc0, acc2 = acc0, acc3 = acc0;

#pragma unroll 5
    for (int k = 0; k < 100; k++) {
        float2 a = *(const float2*)&A_s[k * 128 + bb];
        float4 wv = *(const float4*)&W_s[k * 8 + o4];
        acc0.x += a.x * wv.x; acc0.y += a.y * wv.x;
        acc1.x += a.x * wv.y; acc1.y += a.y * wv.y;
        acc2.x += a.x * wv.z; acc2.y += a.y * wv.z;
        acc3.x += a.x * wv.w; acc3.y += a.y * wv.w;
    }

    int b = blockIdx.z * BATCH + b0 + bb;
    int o0 = og * 8 + o4;
    g_h3p[(b + 0) * 120 + o0 + 0] = acc0.x;
    g_h3p[(b + 1) * 120 + o0 + 0] = acc0.y;
    g_h3p[(b + 0) * 120 + o0 + 1] = acc1.x;
    g_h3p[(b + 1) * 120 + o0 + 1] = acc1.y;
    g_h3p[(b + 0) * 120 + o0 + 2] = acc2.x;
    g_h3p[(b + 1) * 120 + o0 + 2] = acc2.y;
    g_h3p[(b + 0) * 120 + o0 + 3] = acc3.x;
    g_h3p[(b + 1) * 120 + o0 + 3] = acc3.y;
}

// ---------------------------------------------------------------------------
// Kernel D: reduce conv3 partials + bias + relu, then FC2(relu) + FC3.
// ---------------------------------------------------------------------------
__global__ void __launch_bounds__(256) k_fc(const float* __restrict__ b3,
                                            const float* __restrict__ fc2_w,
                                            const float* __restrict__ fc2_b,
                                            const float* __restrict__ fc3_w,
                                            const float* __restrict__ fc3_b,
                                            float* __restrict__ out) {
    __shared__ float w2_s[84 * 121];
    __shared__ float h_s[8][120];
    __shared__ float h84_s[8][84];
    int tid = threadIdx.x;

    for (int l = tid; l < 84 * 120; l += 256) {
        int r = l / 120, c = l % 120;
        w2_s[r * 121 + c] = fc2_w[l];
    }
    __syncthreads();

    int w = tid >> 5, lane = tid & 31;
    int b = blockIdx.x * 8 + w;

#pragma unroll
    for (int m = 0; m < 4; m++) {
        int k = lane + 32 * m;
        if (k < 120) {
            float s = b3[k];
#pragma unroll
            for (int z = 0; z < 4; z++)
                s += g_h3p[(z * BATCH + b) * 120 + k];
            h_s[w][k] = fmaxf(s, 0.f);
        }
    }
    __syncwarp();

#pragma unroll
    for (int m = 0; m < 3; m++) {
        int jj = lane + 32 * m;
        if (jj < 84) {
            float a = fc2_b[jj];
#pragma unroll
            for (int k = 0; k < 120; k++)
                a += h_s[w][k] * w2_s[jj * 121 + k];
            h84_s[w][jj] = fmaxf(a, 0.f);
        }
    }
    __syncwarp();

    if (lane < 10) {
        float a = fc3_b[lane];
#pragma unroll
        for (int k = 0; k < 84; k++)
            a += h84_s[w][k] * fc3_w[lane * 84 + k];
        out[b * 10 + lane] = a;
    }
}

// ---------------------------------------------------------------------------
extern "C" void kernel_launch(void* const* d_in, const int* in_sizes, int n_in,
                              void* d_out, int out_size) {
    const float* x    = (const float*)d_in[0];
    const float* w1   = (const float*)d_in[1];
    const float* b1   = (const float*)d_in[2];
    const float* w2   = (const float*)d_in[3];
    const float* b2   = (const float*)d_in[4];
    const float* w3   = (const float*)d_in[5];
    const float* b3   = (const float*)d_in[6];
    const float* fc2w = (const float*)d_in[7];
    const float* fc2b = (const float*)d_in[8];
    const float* fc3w = (const float*)d_in[9];
    const float* fc3b = (const float*)d_in[10];
    float* out = (float*)d_out;

    k_transpose<<<dim3(96, 32), dim3(32, 8)>>>(x);
    k_conv1<<<dim3(196, 4), 128>>>(w1, b1);
    k_conv2<<<dim3(25, 4, 4), 128>>>(w2, b2);
    k_conv3<<<dim3(8, 15, 4), 128>>>(w3);
    k_fc<<<128, 256>>>(b3, fc2w, fc2b, fc3w, fc3b, out);
}